// round 13
// baseline (speedup 1.0000x reference)
#include <cuda_runtime.h>
#include <math.h>

#define B   32
#define T   64
#define S   400
#define DW  512
#define DM  512
#define DE  512
#define DK  64
#define G3  (3*DM)          // 1536
#define BDM (B*DM)          // 16384
#define PAD_ID 50256
#define NBLK 296

// ---------------- scratch (device globals) ------------------------------------
__device__ float g_emb[T*B*DW];
__device__ float g_pre[B*S*DK];
__device__ float g_encw[B*S];
__device__ float g_cov[B*S];
__device__ float g_hbuf[2][BDM];      // h ping-pong: h[t] at slot t&1
__device__ float g_cbuf[2][BDM];      // ctx ping-pong: ctx[t] at slot t&1
__device__ float g_gxp[8][B*G3];
__device__ float g_ghp[4][B*G3];
__device__ float g_rop[12][BDM];
__device__ volatile unsigned g_flags[NBLK];

#define OFF_PRED      0
#define OFF_ATTNLAST  524288
#define OFF_CTXF      537088
#define OFF_COPY      553472
#define OFF_GATE      1372672
#define OFF_COVP      1374720

__device__ __forceinline__ float tanh_fast(float x) {
    float y; asm("tanh.approx.f32 %0, %1;" : "=f"(y) : "f"(x)); return y;
}
__device__ __forceinline__ float sigmoid_fast(float x) {
    return 1.f / (1.f + __expf(-x));
}

// grid-wide barrier via per-block flags (no same-address atomic serialization).
// release: every thread fences, then thread0 publishes epoch to own slot.
// acquire: threads poll distinct slots in parallel (1-2 slots each), then join.
__device__ __forceinline__ void gbar(unsigned ep) {
    __threadfence();
    __syncthreads();
    if (threadIdx.x == 0) g_flags[blockIdx.x] = ep;
    unsigned i = threadIdx.x;
    if (i < NBLK) { while (g_flags[i] < ep) __nanosleep(32); }
    unsigned j = i + 256;
    if (j < NBLK) { while (g_flags[j] < ep) __nanosleep(32); }
    __threadfence();
    __syncthreads();
}

// 256-thread block reductions (8 warps), sred[8]
__device__ __forceinline__ float bsum256(float v, float* sred) {
    int tid = threadIdx.x;
    __syncthreads();
#pragma unroll
    for (int o = 16; o > 0; o >>= 1) v += __shfl_xor_sync(~0u, v, o);
    if ((tid & 31) == 0) sred[tid >> 5] = v;
    __syncthreads();
    if (tid < 32) {
        float x = (tid < 8) ? sred[tid] : 0.f;
#pragma unroll
        for (int o = 4; o > 0; o >>= 1) x += __shfl_xor_sync(~0u, x, o);
        if (tid == 0) sred[0] = x;
    }
    __syncthreads();
    return sred[0];
}
__device__ __forceinline__ float bmax256(float v, float* sred) {
    int tid = threadIdx.x;
    __syncthreads();
#pragma unroll
    for (int o = 16; o > 0; o >>= 1) v = fmaxf(v, __shfl_xor_sync(~0u, v, o));
    if ((tid & 31) == 0) sred[tid >> 5] = v;
    __syncthreads();
    if (tid < 32) {
        float x = (tid < 8) ? sred[tid] : -1e30f;
#pragma unroll
        for (int o = 4; o > 0; o >>= 1) x = fmaxf(x, __shfl_xor_sync(~0u, x, o));
        if (tid == 0) sred[0] = x;
    }
    __syncthreads();
    return sred[0];
}

// ---------------- one-time kernels -------------------------------------------

__global__ void k_embed(const int* __restrict__ tgt, const float* __restrict__ word_emb)
{
    int row = blockIdx.x;
    int t = row / B, b = row % B;
    int id = tgt[b*T + t];
    const float4* src = (const float4*)(word_emb + (long long)id * DW);
    float4* dst = (float4*)(g_emb + (long long)row * DW);
    dst[threadIdx.x] = src[threadIdx.x];
}

__global__ void k_pre(const float* __restrict__ enc, const float* __restrict__ Wc)
{
    int row = blockIdx.x * 16 + threadIdx.y;
    int n   = threadIdx.x * 4;
    const float* a = enc + (long long)row * DE;
    float4 acc = make_float4(0.f,0.f,0.f,0.f);
#pragma unroll 8
    for (int k = 0; k < DE; k++) {
        float av = a[k];
        float4 wv = *(const float4*)(Wc + k*DK + n);
        acc.x = fmaf(av, wv.x, acc.x); acc.y = fmaf(av, wv.y, acc.y);
        acc.z = fmaf(av, wv.z, acc.z); acc.w = fmaf(av, wv.w, acc.w);
    }
    *(float4*)(g_pre + (long long)row*DK + n) = acc;
}

__global__ void k_encw(const float* __restrict__ enc, const float* __restrict__ W_copy)
{
    int row  = blockIdx.x * 8 + (threadIdx.x >> 5);
    int lane = threadIdx.x & 31;
    const float* e = enc + (size_t)row * DE;
    float acc = 0.f;
#pragma unroll 4
    for (int k = lane; k < DE; k += 32)
        acc = fmaf(e[k], W_copy[DM + k], acc);
#pragma unroll
    for (int o = 16; o > 0; o >>= 1) acc += __shfl_xor_sync(~0u, acc, o);
    if (lane == 0) g_encw[row] = acc;
}

// reset mutable state (every replay): ctx[0]=0, cov=0, flags=0
__global__ void k_init0()
{
    int idx = blockIdx.x * 256 + threadIdx.x;   // 64 blocks -> 0..16383
    g_cbuf[0][idx] = 0.f;
    if (idx < B*S) g_cov[idx] = 0.f;
    if (idx < NBLK) g_flags[idx] = 0u;
}

// ---------------- persistent-kernel phase bodies ------------------------------

// gemm tile: 128-thread unit. mode 0=gx 1=gh 2=readout(step tt)
__device__ __forceinline__ void gemm_tile(
    int mode, int tt, int ks, int n0, int utid,
    const float* __restrict__ Wx, const float* __restrict__ Wh,
    const float* __restrict__ W_read, float* sA /* 32x132 */)
{
    const float* W; int stride;
    int k0 = ks * 128;
    if (mode == 0)      { W = Wx;     stride = G3; }
    else if (mode == 1) { W = Wh;     stride = G3; }
    else                { W = W_read; stride = DM; }
    int hs = (mode == 2) ? ((tt+1)&1) : (tt&1);

#pragma unroll
    for (int j = 0; j < 8; j++) {
        int f = utid + j*128;
        int row = f >> 5;
        int col = (f & 31) * 4;
        int kg = k0 + col;
        const float* src;
        if (mode == 0) {
            src = (kg < 512) ? g_emb + ((size_t)tt*B + row)*DW + kg
                             : g_cbuf[tt&1] + row*DE + (kg - 512);
        } else if (mode == 1) {
            src = g_hbuf[tt&1] + row*DM + kg;
        } else {
            if (kg < 512)       src = g_emb + ((size_t)tt*B + row)*DW + kg;
            else if (kg < 1024) src = g_hbuf[hs] + row*DM + (kg - 512);
            else                src = g_cbuf[hs] + row*DE + (kg - 1024);
        }
        *(float4*)&sA[row*132 + col] = __ldcg((const float4*)src);
    }
    __syncthreads();

    int tx = utid & 7, ty = utid >> 3;
    int n  = n0 + tx * 4;
    int b0 = ty * 2;
    const float* wp = W + (size_t)k0 * stride + n;
    float4 a0 = make_float4(0.f,0.f,0.f,0.f);
    float4 a1 = make_float4(0.f,0.f,0.f,0.f);

#pragma unroll 4
    for (int k = 0; k < 128; k += 4) {
        float4 x0 = *(const float4*)&sA[b0*132 + k];
        float4 x1 = *(const float4*)&sA[(b0+1)*132 + k];
        float4 w0 = *(const float4*)(wp + (size_t)(k  ) * stride);
        float4 w1 = *(const float4*)(wp + (size_t)(k+1) * stride);
        float4 w2 = *(const float4*)(wp + (size_t)(k+2) * stride);
        float4 w3 = *(const float4*)(wp + (size_t)(k+3) * stride);
        a0.x = fmaf(x0.x,w0.x,a0.x); a0.y = fmaf(x0.x,w0.y,a0.y);
        a0.z = fmaf(x0.x,w0.z,a0.z); a0.w = fmaf(x0.x,w0.w,a0.w);
        a1.x = fmaf(x1.x,w0.x,a1.x); a1.y = fmaf(x1.x,w0.y,a1.y);
        a1.z = fmaf(x1.x,w0.z,a1.z); a1.w = fmaf(x1.x,w0.w,a1.w);
        a0.x = fmaf(x0.y,w1.x,a0.x); a0.y = fmaf(x0.y,w1.y,a0.y);
        a0.z = fmaf(x0.y,w1.z,a0.z); a0.w = fmaf(x0.y,w1.w,a0.w);
        a1.x = fmaf(x1.y,w1.x,a1.x); a1.y = fmaf(x1.y,w1.y,a1.y);
        a1.z = fmaf(x1.y,w1.z,a1.z); a1.w = fmaf(x1.y,w1.w,a1.w);
        a0.x = fmaf(x0.z,w2.x,a0.x); a0.y = fmaf(x0.z,w2.y,a0.y);
        a0.z = fmaf(x0.z,w2.z,a0.z); a0.w = fmaf(x0.z,w2.w,a0.w);
        a1.x = fmaf(x1.z,w2.x,a1.x); a1.y = fmaf(x1.z,w2.y,a1.y);
        a1.z = fmaf(x1.z,w2.z,a1.z); a1.w = fmaf(x1.z,w2.w,a1.w);
        a0.x = fmaf(x0.w,w3.x,a0.x); a0.y = fmaf(x0.w,w3.y,a0.y);
        a0.z = fmaf(x0.w,w3.z,a0.z); a0.w = fmaf(x0.w,w3.w,a0.w);
        a1.x = fmaf(x1.w,w3.x,a1.x); a1.y = fmaf(x1.w,w3.y,a1.y);
        a1.z = fmaf(x1.w,w3.z,a1.z); a1.w = fmaf(x1.w,w3.w,a1.w);
    }

    if (mode == 0) {
        __stcg((float4*)(g_gxp[ks] + (size_t)b0*G3 + n),     a0);
        __stcg((float4*)(g_gxp[ks] + (size_t)(b0+1)*G3 + n), a1);
    } else if (mode == 1) {
        __stcg((float4*)(g_ghp[ks] + (size_t)b0*G3 + n),     a0);
        __stcg((float4*)(g_ghp[ks] + (size_t)(b0+1)*G3 + n), a1);
    } else {
        __stcg((float4*)(g_rop[ks] + (size_t)b0*DM + n),     a0);
        __stcg((float4*)(g_rop[ks] + (size_t)(b0+1)*DM + n), a1);
    }
}

// attn for batch row b, 256 threads
__device__ void attn_task(int t, int b,
    const int* __restrict__ src_seq,
    const float* __restrict__ Wq, const float* __restrict__ w_cov,
    const float* __restrict__ v_att, const float* __restrict__ W_copy,
    const float* __restrict__ b_copy, const float* __restrict__ bx,
    const float* __restrict__ bh, float* __restrict__ out, float* sm)
{
    int tid = threadIdx.x;
    float* sh   = sm;          // 512
    float* sq   = sm + 512;    // 64
    float* sqp  = sm + 576;    // 256
    float* swc  = sm + 832;    // 64
    float* sva  = sm + 896;    // 64
    float* ss   = sm + 960;    // 400
    float* sred = sm + 1368;   // 8

    // GRU gates (2 j's per thread)
#pragma unroll
    for (int jj = 0; jj < 2; jj++) {
        int j = tid + jj*256;
        size_t base = (size_t)b*G3 + j;
        float gxr = bx[j],      ghr = bh[j];
        float gxz = bx[DM+j],   ghz = bh[DM+j];
        float gxn = bx[2*DM+j], ghn = bh[2*DM+j];
#pragma unroll
        for (int p = 0; p < 8; p++) {
            gxr += __ldcg(&g_gxp[p][base]);
            gxz += __ldcg(&g_gxp[p][base + DM]);
            gxn += __ldcg(&g_gxp[p][base + 2*DM]);
        }
#pragma unroll
        for (int p = 0; p < 4; p++) {
            ghr += __ldcg(&g_ghp[p][base]);
            ghz += __ldcg(&g_ghp[p][base + DM]);
            ghn += __ldcg(&g_ghp[p][base + 2*DM]);
        }
        float r  = sigmoid_fast(gxr + ghr);
        float z  = sigmoid_fast(gxz + ghz);
        float nn = tanh_fast(gxn + r * ghn);
        float ho = __ldcg(&g_hbuf[t&1][b*DM + j]);
        float hn = (1.f - z) * nn + z * ho;
        sh[j] = hn;
        __stcg(&g_hbuf[(t+1)&1][b*DM + j], hn);
    }
    __syncthreads();

    // q = h @ Wq, split-K 4x128
    {
        int j = tid & 63, p = tid >> 6;
        float acc = 0.f;
#pragma unroll 8
        for (int k = p*128; k < (p+1)*128; k++)
            acc = fmaf(sh[k], Wq[k*DK + j], acc);
        sqp[p*64 + j] = acc;
        if (tid < 64)        swc[tid]      = w_cov[tid];
        else if (tid < 128)  sva[tid - 64] = v_att[tid - 64];
    }
    __syncthreads();
    if (tid < 64) sq[tid] = sqp[tid] + sqp[64+tid] + sqp[128+tid] + sqp[192+tid];
    __syncthreads();

    // scores at s0 = tid (always valid), s1 = tid+256 (valid if < S)
    int s0 = tid, s1 = tid + 256;
    float cv0 = g_cov[b*S + s0];
    float cv1 = (s1 < S) ? g_cov[b*S + s1] : 0.f;
    {
        const float4* pr = (const float4*)(g_pre + ((size_t)b*S + s0) * DK);
        float acc = 0.f;
#pragma unroll
        for (int k4 = 0; k4 < 16; k4++) {
            float4 p = pr[k4]; int k = k4*4;
            acc = fmaf(tanh_fast(p.x + sq[k  ] + cv0*swc[k  ]), sva[k  ], acc);
            acc = fmaf(tanh_fast(p.y + sq[k+1] + cv0*swc[k+1]), sva[k+1], acc);
            acc = fmaf(tanh_fast(p.z + sq[k+2] + cv0*swc[k+2]), sva[k+2], acc);
            acc = fmaf(tanh_fast(p.w + sq[k+3] + cv0*swc[k+3]), sva[k+3], acc);
        }
        if (src_seq[b*S + s0] == PAD_ID) acc = -1e9f;
        ss[s0] = acc;
    }
    if (s1 < S) {
        const float4* pr = (const float4*)(g_pre + ((size_t)b*S + s1) * DK);
        float acc = 0.f;
#pragma unroll
        for (int k4 = 0; k4 < 16; k4++) {
            float4 p = pr[k4]; int k = k4*4;
            acc = fmaf(tanh_fast(p.x + sq[k  ] + cv1*swc[k  ]), sva[k  ], acc);
            acc = fmaf(tanh_fast(p.y + sq[k+1] + cv1*swc[k+1]), sva[k+1], acc);
            acc = fmaf(tanh_fast(p.z + sq[k+2] + cv1*swc[k+2]), sva[k+2], acc);
            acc = fmaf(tanh_fast(p.w + sq[k+3] + cv1*swc[k+3]), sva[k+3], acc);
        }
        if (src_seq[b*S + s1] == PAD_ID) acc = -1e9f;
        ss[s1] = acc;
    }

    float m = bmax256(fmaxf(ss[s0], (s1 < S) ? ss[s1] : -1e30f), sred);
    float e0 = __expf(ss[s0] - m);
    float e1 = (s1 < S) ? __expf(ss[s1] - m) : 0.f;
    float inv = 1.f / bsum256(e0 + e1, sred);

    float tden = fmaxf((float)t, 1.f);
    float cl = 0.f;
    float a0 = e0 * inv;
    cl += fminf(a0, cv0 / tden);
    g_cov[b*S + s0] = cv0 + a0;
    __stcg(&out[OFF_COPY + (size_t)b*T*S + (size_t)t*S + s0], a0);
    if (t == T-1) out[OFF_ATTNLAST + b*S + s0] = a0;
    float a1 = 0.f;
    if (s1 < S) {
        a1 = e1 * inv;
        cl += fminf(a1, cv1 / tden);
        g_cov[b*S + s1] = cv1 + a1;
        __stcg(&out[OFF_COPY + (size_t)b*T*S + (size_t)t*S + s1], a1);
        if (t == T-1) out[OFF_ATTNLAST + b*S + s1] = a1;
    }
    float clsum = bsum256(cl, sred);
    if (tid == 0) out[OFF_COVP + b*T + t] = clsum;

    // copy gate: h.W1 + attn.encw
    float g = sh[tid] * W_copy[tid] + sh[tid+256] * W_copy[tid+256];
    g = fmaf(a0, g_encw[b*S + s0], g);
    if (s1 < S) g = fmaf(a1, g_encw[b*S + s1], g);
    float gs = bsum256(g, sred);
    if (tid == 0) out[OFF_GATE + b*T + t] = sigmoid_fast(gs + b_copy[0]);
}

// ctx[t] for task = blockIdx (0..255): b = task>>3, q = task&7
__device__ void ctx_task(int t, int task, const float* __restrict__ enc,
                         float* __restrict__ out, float* sm)
{
    int b = task >> 3, q = task & 7;
    int tid = threadIdx.x;
    int sg = tid >> 4, c4 = tid & 15;
    int d4 = q*16 + c4;
    float*  sa   = sm;
    float4* part = (float4*)(sm + 512);   // [16][17]

    for (int s = tid; s < S; s += 256)
        sa[s] = __ldcg(&out[OFF_COPY + (size_t)b*T*S + (size_t)(t-1)*S + s]);
    __syncthreads();

    const float4* e4 = (const float4*)(enc + (size_t)b*S*DE);
    float4 acc = make_float4(0.f,0.f,0.f,0.f);
    int s0 = sg * 25;
#pragma unroll 5
    for (int i = 0; i < 25; i++) {
        int s = s0 + i;
        float a = sa[s];
        float4 v = e4[(size_t)s*(DE/4) + d4];
        acc.x = fmaf(a,v.x,acc.x); acc.y = fmaf(a,v.y,acc.y);
        acc.z = fmaf(a,v.z,acc.z); acc.w = fmaf(a,v.w,acc.w);
    }
    part[sg*17 + c4] = acc;
    __syncthreads();
#pragma unroll
    for (int st = 8; st > 0; st >>= 1) {
        if (sg < st) {
            float4 o = part[(sg+st)*17 + c4];
            acc.x += o.x; acc.y += o.y; acc.z += o.z; acc.w += o.w;
            part[sg*17 + c4] = acc;
        }
        __syncthreads();
    }
    if (sg == 0) {
        __stcg((float4*)(g_cbuf[t&1] + b*DE + d4*4), acc);
        if (t == T)
            *(float4*)(out + OFF_CTXF + b*DE + d4*4) = acc;
    }
}

__device__ void rored_task(int tr, int b, const float* __restrict__ b_read,
                           float* __restrict__ out)
{
    int tid = threadIdx.x;
    float2 acc = *(const float2*)(b_read + tid*2);
#pragma unroll
    for (int p = 0; p < 12; p++) {
        float2 v = __ldcg((const float2*)(g_rop[p] + (size_t)b*DM + tid*2));
        acc.x += v.x; acc.y += v.y;
    }
    out[OFF_PRED + ((size_t)b*T + tr) * (DM/2) + tid] = fmaxf(acc.x, acc.y);
}

// h0 = tanh(hidden @ W_init + b_init): blocks 0..255, 64 outputs/block
__device__ void h0_task(const float* __restrict__ hidden,
                        const float* __restrict__ W_init,
                        const float* __restrict__ b_init, float* sm)
{
    int tid = threadIdx.x;
    int o = blockIdx.x * 64 + (tid >> 2);
    int part = tid & 3;
    int bb = o >> 9, j = o & 511;
    float acc = 0.f;
#pragma unroll 8
    for (int k = part*128; k < part*128 + 128; k++)
        acc = fmaf(hidden[bb*DE + k], W_init[k*DM + j], acc);
    sm[tid] = acc;
    __syncthreads();
    if (part == 0) {
        float v = sm[tid] + sm[tid+1] + sm[tid+2] + sm[tid+3] + b_init[j];
        __stcg(&g_hbuf[0][o], tanhf(v));
    }
}

// ---------------- the persistent kernel ---------------------------------------
__global__ void __launch_bounds__(256, 2)
k_persist(const int* __restrict__ src_seq,
          const float* __restrict__ enc,
          const float* __restrict__ hidden,
          const float* __restrict__ W_init, const float* __restrict__ b_init,
          const float* __restrict__ Wx, const float* __restrict__ Wh,
          const float* __restrict__ bx, const float* __restrict__ bh,
          const float* __restrict__ Wq, const float* __restrict__ w_cov,
          const float* __restrict__ v_att,
          const float* __restrict__ W_copy, const float* __restrict__ b_copy,
          const float* __restrict__ W_read, const float* __restrict__ b_read,
          float* __restrict__ out)
{
    extern __shared__ float sm[];       // 2 * 32*132 floats = 33792 B
    int bid = blockIdx.x;
    int tid = threadIdx.x;
    int half = tid >> 7;
    int utid = tid & 127;
    float* sA = sm + half * (32*132);

    unsigned ep = 0;

    for (int t = 0; t <= T; t++) {
        // ---- P1: ctx[t] (+ h0 at t=0) + rored(t-2) ----
        if (t == 0) {
            if (bid < 256) h0_task(hidden, W_init, b_init, sm);
        } else {
            if (bid < 256) ctx_task(t, bid, enc, out, sm);
            else if (t >= 2 && bid < 288) rored_task(t-2, bid - 256, b_read, out);
        }
        ep++; gbar(ep);
        if (t == T) break;

        // ---- P2: gx + gh (576 units, stable mapping -> L1-resident weights) --
        if (bid < 288) {
            int unit = bid*2 + half;
            if (unit < 384) gemm_tile(0, t, unit & 7, (unit >> 3) * 32, utid,
                                      Wx, Wh, W_read, sA);
            else {
                int u = unit - 384;
                gemm_tile(1, t, u & 3, (u >> 2) * 32, utid, Wx, Wh, W_read, sA);
            }
        }
        ep++; gbar(ep);

        // ---- P3: attn(t) on blocks 0..31 ; ro(t-1) on blocks 32..127 ----
        if (bid < 32) {
            attn_task(t, bid, src_seq, Wq, w_cov, v_att, W_copy, b_copy,
                      bx, bh, out, sm);
        } else if (t >= 1 && bid < 128) {
            int r = (bid - 32)*2 + half;     // 0..191
            gemm_tile(2, t-1, r % 12, (r / 12) * 32, utid, Wx, Wh, W_read, sA);
        }
        ep++; gbar(ep);
    }

    // ---- tail: ro(T-1), then rored(T-1) ----
    if (bid >= 32 && bid < 128) {
        int r = (bid - 32)*2 + half;
        gemm_tile(2, T-1, r % 12, (r / 12) * 32, utid, Wx, Wh, W_read, sA);
    }
    ep++; gbar(ep);
    if (bid < 32) rored_task(T-1, bid, b_read, out);
}

// ---------------- launch ------------------------------------------------------

extern "C" void kernel_launch(void* const* d_in, const int* in_sizes, int n_in,
                              void* d_out, int out_size)
{
    const int*   tgt      = (const int*)  d_in[0];
    const int*   src      = (const int*)  d_in[1];
    const float* enc      = (const float*)d_in[2];
    const float* hidden   = (const float*)d_in[3];
    const float* word_emb = (const float*)d_in[4];
    const float* W_init   = (const float*)d_in[5];
    const float* b_init   = (const float*)d_in[6];
    const float* Wx       = (const float*)d_in[7];
    const float* Wh       = (const float*)d_in[8];
    const float* bx       = (const float*)d_in[9];
    const float* bh       = (const float*)d_in[10];
    const float* Wc       = (const float*)d_in[11];
    const float* Wq       = (const float*)d_in[12];
    const float* w_cov    = (const float*)d_in[13];
    const float* v_att    = (const float*)d_in[14];
    const float* W_copy   = (const float*)d_in[15];
    const float* b_copy   = (const float*)d_in[16];
    const float* W_read   = (const float*)d_in[17];
    const float* b_read   = (const float*)d_in[18];
    float* out = (float*)d_out;

    k_embed<<<T*B, 128>>>(tgt, word_emb);
    k_pre<<<(B*S)/16, dim3(16,16)>>>(enc, Wc);
    k_encw<<<(B*S)/8, 256>>>(enc, W_copy);
    k_init0<<<64, 256>>>();

    k_persist<<<NBLK, 256, 2*32*132*sizeof(float)>>>(
        src, enc, hidden, W_init, b_init, Wx, Wh, bx, bh,
        Wq, w_cov, v_att, W_copy, b_copy, W_read, b_read, out);
}

// round 14
// speedup vs baseline: 2.2517x; 2.2517x over previous
#include <cuda_runtime.h>
#include <math.h>

#define B   32
#define T   64
#define S   400
#define DW  512
#define DM  512
#define DE  512
#define DK  64
#define G3  (3*DM)          // 1536
#define BDM (B*DM)          // 16384
#define PAD_ID 50256
#define NBLK 296

// ---------------- scratch (device globals) ------------------------------------
__device__ float g_emb[T*B*DW];
__device__ float g_pre[B*S*DK];
__device__ float g_encw[B*S];
__device__ float g_cov[B*S];
__device__ float g_hbuf[2][BDM];      // h ping-pong: h[t] at slot t&1
__device__ float g_cbuf[2][BDM];      // ctx ping-pong: ctx[t] at slot t&1
__device__ float g_gxp[8][B*G3];
__device__ float g_ghp[4][B*G3];
__device__ float g_rop[12][BDM];
__device__ unsigned g_barcnt;

#define OFF_PRED      0
#define OFF_ATTNLAST  524288
#define OFF_CTXF      537088
#define OFF_COPY      553472
#define OFF_GATE      1372672
#define OFF_COVP      1374720

__device__ __forceinline__ float tanh_fast(float x) {
    float y; asm("tanh.approx.f32 %0, %1;" : "=f"(y) : "f"(x)); return y;
}
__device__ __forceinline__ float sigmoid_fast(float x) {
    return 1.f / (1.f + __expf(-x));
}

// grid-wide barrier (R12-proven): atomic arrival + single-line poll per block
__device__ __forceinline__ void gbar(unsigned target) {
    __syncthreads();
    if (threadIdx.x == 0) {
        __threadfence();
        atomicAdd(&g_barcnt, 1u);
        volatile unsigned* p = &g_barcnt;
        while (*p < target) __nanosleep(64);
        __threadfence();
    }
    __syncthreads();
}

// 256-thread block reductions (8 warps), sred[8]
__device__ __forceinline__ float bsum256(float v, float* sred) {
    int tid = threadIdx.x;
    __syncthreads();
#pragma unroll
    for (int o = 16; o > 0; o >>= 1) v += __shfl_xor_sync(~0u, v, o);
    if ((tid & 31) == 0) sred[tid >> 5] = v;
    __syncthreads();
    if (tid < 32) {
        float x = (tid < 8) ? sred[tid] : 0.f;
#pragma unroll
        for (int o = 4; o > 0; o >>= 1) x += __shfl_xor_sync(~0u, x, o);
        if (tid == 0) sred[0] = x;
    }
    __syncthreads();
    return sred[0];
}
__device__ __forceinline__ float bmax256(float v, float* sred) {
    int tid = threadIdx.x;
    __syncthreads();
#pragma unroll
    for (int o = 16; o > 0; o >>= 1) v = fmaxf(v, __shfl_xor_sync(~0u, v, o));
    if ((tid & 31) == 0) sred[tid >> 5] = v;
    __syncthreads();
    if (tid < 32) {
        float x = (tid < 8) ? sred[tid] : -1e30f;
#pragma unroll
        for (int o = 4; o > 0; o >>= 1) x = fmaxf(x, __shfl_xor_sync(~0u, x, o));
        if (tid == 0) sred[0] = x;
    }
    __syncthreads();
    return sred[0];
}

// ---------------- one-time kernels -------------------------------------------

__global__ void k_embed(const int* __restrict__ tgt, const float* __restrict__ word_emb)
{
    int row = blockIdx.x;
    int t = row / B, b = row % B;
    int id = tgt[b*T + t];
    const float4* src = (const float4*)(word_emb + (long long)id * DW);
    float4* dst = (float4*)(g_emb + (long long)row * DW);
    dst[threadIdx.x] = src[threadIdx.x];
}

__global__ void k_pre(const float* __restrict__ enc, const float* __restrict__ Wc)
{
    int row = blockIdx.x * 16 + threadIdx.y;
    int n   = threadIdx.x * 4;
    const float* a = enc + (long long)row * DE;
    float4 acc = make_float4(0.f,0.f,0.f,0.f);
#pragma unroll 8
    for (int k = 0; k < DE; k++) {
        float av = a[k];
        float4 wv = *(const float4*)(Wc + k*DK + n);
        acc.x = fmaf(av, wv.x, acc.x); acc.y = fmaf(av, wv.y, acc.y);
        acc.z = fmaf(av, wv.z, acc.z); acc.w = fmaf(av, wv.w, acc.w);
    }
    *(float4*)(g_pre + (long long)row*DK + n) = acc;
}

__global__ void k_encw(const float* __restrict__ enc, const float* __restrict__ W_copy)
{
    int row  = blockIdx.x * 8 + (threadIdx.x >> 5);
    int lane = threadIdx.x & 31;
    const float* e = enc + (size_t)row * DE;
    float acc = 0.f;
#pragma unroll 4
    for (int k = lane; k < DE; k += 32)
        acc = fmaf(e[k], W_copy[DM + k], acc);
#pragma unroll
    for (int o = 16; o > 0; o >>= 1) acc += __shfl_xor_sync(~0u, acc, o);
    if (lane == 0) g_encw[row] = acc;
}

// reset mutable state (every replay): ctx[0]=0, cov=0, barrier=0
__global__ void k_init0()
{
    int idx = blockIdx.x * 256 + threadIdx.x;   // 64 blocks -> 0..16383
    g_cbuf[0][idx] = 0.f;
    if (idx < B*S) g_cov[idx] = 0.f;
    if (idx == 0)  g_barcnt = 0u;
}

// ---------------- persistent-kernel phase bodies ------------------------------

// gemm tile: 128-thread unit. mode 0=gx 1=gh 2=readout(step tt)
__device__ __forceinline__ void gemm_tile(
    int mode, int tt, int ks, int n0, int utid,
    const float* __restrict__ Wx, const float* __restrict__ Wh,
    const float* __restrict__ W_read, float* sA /* 32x132 */)
{
    const float* W; int stride;
    int k0 = ks * 128;
    if (mode == 0)      { W = Wx;     stride = G3; }
    else if (mode == 1) { W = Wh;     stride = G3; }
    else                { W = W_read; stride = DM; }
    int hs = (mode == 2) ? ((tt+1)&1) : (tt&1);

#pragma unroll
    for (int j = 0; j < 8; j++) {
        int f = utid + j*128;
        int row = f >> 5;
        int col = (f & 31) * 4;
        int kg = k0 + col;
        const float* src;
        if (mode == 0) {
            src = (kg < 512) ? g_emb + ((size_t)tt*B + row)*DW + kg
                             : g_cbuf[tt&1] + row*DE + (kg - 512);
        } else if (mode == 1) {
            src = g_hbuf[tt&1] + row*DM + kg;
        } else {
            if (kg < 512)       src = g_emb + ((size_t)tt*B + row)*DW + kg;
            else if (kg < 1024) src = g_hbuf[hs] + row*DM + (kg - 512);
            else                src = g_cbuf[hs] + row*DE + (kg - 1024);
        }
        *(float4*)&sA[row*132 + col] = __ldcg((const float4*)src);
    }
    __syncthreads();

    int tx = utid & 7, ty = utid >> 3;
    int n  = n0 + tx * 4;
    int b0 = ty * 2;
    const float* wp = W + (size_t)k0 * stride + n;
    float4 a0 = make_float4(0.f,0.f,0.f,0.f);
    float4 a1 = make_float4(0.f,0.f,0.f,0.f);

#pragma unroll 4
    for (int k = 0; k < 128; k += 4) {
        float4 x0 = *(const float4*)&sA[b0*132 + k];
        float4 x1 = *(const float4*)&sA[(b0+1)*132 + k];
        float4 w0 = *(const float4*)(wp + (size_t)(k  ) * stride);
        float4 w1 = *(const float4*)(wp + (size_t)(k+1) * stride);
        float4 w2 = *(const float4*)(wp + (size_t)(k+2) * stride);
        float4 w3 = *(const float4*)(wp + (size_t)(k+3) * stride);
        a0.x = fmaf(x0.x,w0.x,a0.x); a0.y = fmaf(x0.x,w0.y,a0.y);
        a0.z = fmaf(x0.x,w0.z,a0.z); a0.w = fmaf(x0.x,w0.w,a0.w);
        a1.x = fmaf(x1.x,w0.x,a1.x); a1.y = fmaf(x1.x,w0.y,a1.y);
        a1.z = fmaf(x1.x,w0.z,a1.z); a1.w = fmaf(x1.x,w0.w,a1.w);
        a0.x = fmaf(x0.y,w1.x,a0.x); a0.y = fmaf(x0.y,w1.y,a0.y);
        a0.z = fmaf(x0.y,w1.z,a0.z); a0.w = fmaf(x0.y,w1.w,a0.w);
        a1.x = fmaf(x1.y,w1.x,a1.x); a1.y = fmaf(x1.y,w1.y,a1.y);
        a1.z = fmaf(x1.y,w1.z,a1.z); a1.w = fmaf(x1.y,w1.w,a1.w);
        a0.x = fmaf(x0.z,w2.x,a0.x); a0.y = fmaf(x0.z,w2.y,a0.y);
        a0.z = fmaf(x0.z,w2.z,a0.z); a0.w = fmaf(x0.z,w2.w,a0.w);
        a1.x = fmaf(x1.z,w2.x,a1.x); a1.y = fmaf(x1.z,w2.y,a1.y);
        a1.z = fmaf(x1.z,w2.z,a1.z); a1.w = fmaf(x1.z,w2.w,a1.w);
        a0.x = fmaf(x0.w,w3.x,a0.x); a0.y = fmaf(x0.w,w3.y,a0.y);
        a0.z = fmaf(x0.w,w3.z,a0.z); a0.w = fmaf(x0.w,w3.w,a0.w);
        a1.x = fmaf(x1.w,w3.x,a1.x); a1.y = fmaf(x1.w,w3.y,a1.y);
        a1.z = fmaf(x1.w,w3.z,a1.z); a1.w = fmaf(x1.w,w3.w,a1.w);
    }

    if (mode == 0) {
        __stcg((float4*)(g_gxp[ks] + (size_t)b0*G3 + n),     a0);
        __stcg((float4*)(g_gxp[ks] + (size_t)(b0+1)*G3 + n), a1);
    } else if (mode == 1) {
        __stcg((float4*)(g_ghp[ks] + (size_t)b0*G3 + n),     a0);
        __stcg((float4*)(g_ghp[ks] + (size_t)(b0+1)*G3 + n), a1);
    } else {
        __stcg((float4*)(g_rop[ks] + (size_t)b0*DM + n),     a0);
        __stcg((float4*)(g_rop[ks] + (size_t)(b0+1)*DM + n), a1);
    }
}

// attn for batch row b, 256 threads
__device__ void attn_task(int t, int b,
    const int* __restrict__ src_seq,
    const float* __restrict__ Wq, const float* __restrict__ w_cov,
    const float* __restrict__ v_att, const float* __restrict__ W_copy,
    const float* __restrict__ b_copy, const float* __restrict__ bx,
    const float* __restrict__ bh, float* __restrict__ out, float* sm)
{
    int tid = threadIdx.x;
    float* sh   = sm;          // 512
    float* sq   = sm + 512;    // 64
    float* sqp  = sm + 576;    // 1024 (16 parts x 64)
    float* swc  = sm + 1600;   // 64
    float* sva  = sm + 1664;   // 64
    float* ss   = sm + 1728;   // 400
    float* sred = sm + 2136;   // 8

    // GRU gates (2 j's per thread) + small vec loads
#pragma unroll
    for (int jj = 0; jj < 2; jj++) {
        int j = tid + jj*256;
        size_t base = (size_t)b*G3 + j;
        float gxr = bx[j],      ghr = bh[j];
        float gxz = bx[DM+j],   ghz = bh[DM+j];
        float gxn = bx[2*DM+j], ghn = bh[2*DM+j];
#pragma unroll
        for (int p = 0; p < 8; p++) {
            gxr += __ldcg(&g_gxp[p][base]);
            gxz += __ldcg(&g_gxp[p][base + DM]);
            gxn += __ldcg(&g_gxp[p][base + 2*DM]);
        }
#pragma unroll
        for (int p = 0; p < 4; p++) {
            ghr += __ldcg(&g_ghp[p][base]);
            ghz += __ldcg(&g_ghp[p][base + DM]);
            ghn += __ldcg(&g_ghp[p][base + 2*DM]);
        }
        float r  = sigmoid_fast(gxr + ghr);
        float z  = sigmoid_fast(gxz + ghz);
        float nn = tanh_fast(gxn + r * ghn);
        float ho = __ldcg(&g_hbuf[t&1][b*DM + j]);
        float hn = (1.f - z) * nn + z * ho;
        sh[j] = hn;
        __stcg(&g_hbuf[(t+1)&1][b*DM + j], hn);
    }
    if (tid < 64)             swc[tid]      = w_cov[tid];
    else if (tid < 128)       sva[tid - 64] = v_att[tid - 64];
    __syncthreads();

    // q = h @ Wq, split-K 16 x 32, vectorized Wq loads (float4 over cols)
    {
        int p  = tid >> 4;         // k-part 0..15
        int j4 = tid & 15;         // float4 col group
        float4 acc = make_float4(0.f,0.f,0.f,0.f);
#pragma unroll 8
        for (int k = p*32; k < p*32 + 32; k++) {
            float hk = sh[k];
            float4 w = *(const float4*)(Wq + k*DK + j4*4);
            acc.x = fmaf(hk,w.x,acc.x); acc.y = fmaf(hk,w.y,acc.y);
            acc.z = fmaf(hk,w.z,acc.z); acc.w = fmaf(hk,w.w,acc.w);
        }
        *(float4*)&sqp[p*64 + j4*4] = acc;
    }
    __syncthreads();
    if (tid < 64) {
        float s = 0.f;
#pragma unroll
        for (int p = 0; p < 16; p++) s += sqp[p*64 + tid];
        sq[tid] = s;
    }
    __syncthreads();

    // scores at s0 = tid, s1 = tid+256 (pre via L2 to avoid L1 pollution)
    int s0 = tid, s1 = tid + 256;
    float cv0 = g_cov[b*S + s0];
    float cv1 = (s1 < S) ? g_cov[b*S + s1] : 0.f;
    {
        const float4* pr = (const float4*)(g_pre + ((size_t)b*S + s0) * DK);
        float acc = 0.f;
#pragma unroll
        for (int k4 = 0; k4 < 16; k4++) {
            float4 p = __ldcg(pr + k4); int k = k4*4;
            acc = fmaf(tanh_fast(p.x + sq[k  ] + cv0*swc[k  ]), sva[k  ], acc);
            acc = fmaf(tanh_fast(p.y + sq[k+1] + cv0*swc[k+1]), sva[k+1], acc);
            acc = fmaf(tanh_fast(p.z + sq[k+2] + cv0*swc[k+2]), sva[k+2], acc);
            acc = fmaf(tanh_fast(p.w + sq[k+3] + cv0*swc[k+3]), sva[k+3], acc);
        }
        if (src_seq[b*S + s0] == PAD_ID) acc = -1e9f;
        ss[s0] = acc;
    }
    if (s1 < S) {
        const float4* pr = (const float4*)(g_pre + ((size_t)b*S + s1) * DK);
        float acc = 0.f;
#pragma unroll
        for (int k4 = 0; k4 < 16; k4++) {
            float4 p = __ldcg(pr + k4); int k = k4*4;
            acc = fmaf(tanh_fast(p.x + sq[k  ] + cv1*swc[k  ]), sva[k  ], acc);
            acc = fmaf(tanh_fast(p.y + sq[k+1] + cv1*swc[k+1]), sva[k+1], acc);
            acc = fmaf(tanh_fast(p.z + sq[k+2] + cv1*swc[k+2]), sva[k+2], acc);
            acc = fmaf(tanh_fast(p.w + sq[k+3] + cv1*swc[k+3]), sva[k+3], acc);
        }
        if (src_seq[b*S + s1] == PAD_ID) acc = -1e9f;
        ss[s1] = acc;
    }

    float m = bmax256(fmaxf(ss[s0], (s1 < S) ? ss[s1] : -1e30f), sred);
    float e0 = __expf(ss[s0] - m);
    float e1 = (s1 < S) ? __expf(ss[s1] - m) : 0.f;
    float inv = 1.f / bsum256(e0 + e1, sred);

    float tden = fmaxf((float)t, 1.f);
    float cl = 0.f;
    float a0 = e0 * inv;
    cl += fminf(a0, cv0 / tden);
    g_cov[b*S + s0] = cv0 + a0;
    __stcg(&out[OFF_COPY + (size_t)b*T*S + (size_t)t*S + s0], a0);
    if (t == T-1) out[OFF_ATTNLAST + b*S + s0] = a0;
    float a1 = 0.f;
    if (s1 < S) {
        a1 = e1 * inv;
        cl += fminf(a1, cv1 / tden);
        g_cov[b*S + s1] = cv1 + a1;
        __stcg(&out[OFF_COPY + (size_t)b*T*S + (size_t)t*S + s1], a1);
        if (t == T-1) out[OFF_ATTNLAST + b*S + s1] = a1;
    }
    float clsum = bsum256(cl, sred);
    if (tid == 0) out[OFF_COVP + b*T + t] = clsum;

    // copy gate: h.W1 + attn.encw
    float g = sh[tid] * W_copy[tid] + sh[tid+256] * W_copy[tid+256];
    g = fmaf(a0, g_encw[b*S + s0], g);
    if (s1 < S) g = fmaf(a1, g_encw[b*S + s1], g);
    float gs = bsum256(g, sred);
    if (tid == 0) out[OFF_GATE + b*T + t] = sigmoid_fast(gs + b_copy[0]);
}

// ctx[t] for task = blockIdx (0..255): b = task>>3, q = task&7
// enc loaded with __ldcs (streaming) -> does NOT evict L1-resident weights
__device__ void ctx_task(int t, int task, const float* __restrict__ enc,
                         float* __restrict__ out, float* sm)
{
    int b = task >> 3, q = task & 7;
    int tid = threadIdx.x;
    int sg = tid >> 4, c4 = tid & 15;
    int d4 = q*16 + c4;
    float*  sa   = sm;
    float4* part = (float4*)(sm + 512);   // [16][17]

    for (int s = tid; s < S; s += 256)
        sa[s] = __ldcg(&out[OFF_COPY + (size_t)b*T*S + (size_t)(t-1)*S + s]);
    __syncthreads();

    const float4* e4 = (const float4*)(enc + (size_t)b*S*DE);
    float4 acc = make_float4(0.f,0.f,0.f,0.f);
    int s0 = sg * 25;
#pragma unroll 5
    for (int i = 0; i < 25; i++) {
        int s = s0 + i;
        float a = sa[s];
        float4 v = __ldcs(e4 + (size_t)s*(DE/4) + d4);
        acc.x = fmaf(a,v.x,acc.x); acc.y = fmaf(a,v.y,acc.y);
        acc.z = fmaf(a,v.z,acc.z); acc.w = fmaf(a,v.w,acc.w);
    }
    part[sg*17 + c4] = acc;
    __syncthreads();
#pragma unroll
    for (int st = 8; st > 0; st >>= 1) {
        if (sg < st) {
            float4 o = part[(sg+st)*17 + c4];
            acc.x += o.x; acc.y += o.y; acc.z += o.z; acc.w += o.w;
            part[sg*17 + c4] = acc;
        }
        __syncthreads();
    }
    if (sg == 0) {
        __stcg((float4*)(g_cbuf[t&1] + b*DE + d4*4), acc);
        if (t == T)
            *(float4*)(out + OFF_CTXF + b*DE + d4*4) = acc;
    }
}

__device__ void rored_task(int tr, int b, const float* __restrict__ b_read,
                           float* __restrict__ out)
{
    int tid = threadIdx.x;
    float2 acc = *(const float2*)(b_read + tid*2);
#pragma unroll
    for (int p = 0; p < 12; p++) {
        float2 v = __ldcg((const float2*)(g_rop[p] + (size_t)b*DM + tid*2));
        acc.x += v.x; acc.y += v.y;
    }
    out[OFF_PRED + ((size_t)b*T + tr) * (DM/2) + tid] = fmaxf(acc.x, acc.y);
}

// h0 = tanh(hidden @ W_init + b_init): blocks 0..255, 64 outputs/block
__device__ void h0_task(const float* __restrict__ hidden,
                        const float* __restrict__ W_init,
                        const float* __restrict__ b_init, float* sm)
{
    int tid = threadIdx.x;
    int o = blockIdx.x * 64 + (tid >> 2);
    int part = tid & 3;
    int bb = o >> 9, j = o & 511;
    float acc = 0.f;
#pragma unroll 8
    for (int k = part*128; k < part*128 + 128; k++)
        acc = fmaf(hidden[bb*DE + k], W_init[k*DM + j], acc);
    sm[tid] = acc;
    __syncthreads();
    if (part == 0) {
        float v = sm[tid] + sm[tid+1] + sm[tid+2] + sm[tid+3] + b_init[j];
        __stcg(&g_hbuf[0][o], tanhf(v));
    }
}

// ---------------- the persistent kernel ---------------------------------------
__global__ void __launch_bounds__(256, 2)
k_persist(const int* __restrict__ src_seq,
          const float* __restrict__ enc,
          const float* __restrict__ hidden,
          const float* __restrict__ W_init, const float* __restrict__ b_init,
          const float* __restrict__ Wx, const float* __restrict__ Wh,
          const float* __restrict__ bx, const float* __restrict__ bh,
          const float* __restrict__ Wq, const float* __restrict__ w_cov,
          const float* __restrict__ v_att,
          const float* __restrict__ W_copy, const float* __restrict__ b_copy,
          const float* __restrict__ W_read, const float* __restrict__ b_read,
          float* __restrict__ out)
{
    extern __shared__ float sm[];       // 33792 B
    int bid = blockIdx.x;
    int tid = threadIdx.x;
    int half = tid >> 7;
    int utid = tid & 127;
    float* sA = sm + half * (32*132);

    unsigned ep = 0;

    for (int t = 0; t <= T; t++) {
        // ---- P1: ctx[t] (h0 at t=0); pure, short phase ----
        if (t == 0) {
            if (bid < 256) h0_task(hidden, W_init, b_init, sm);
        } else {
            if (bid < 256) ctx_task(t, bid, enc, out, sm);
        }
        ep++; gbar(ep * NBLK);
        if (t == T) break;

        // ---- P2: gx + gh (576 units, stable mapping -> L1-resident weights) --
        if (bid < 288) {
            int unit = bid*2 + half;
            if (unit < 384) gemm_tile(0, t, unit & 7, (unit >> 3) * 32, utid,
                                      Wx, Wh, W_read, sA);
            else {
                int u = unit - 384;
                gemm_tile(1, t, u & 3, (u >> 2) * 32, utid, Wx, Wh, W_read, sA);
            }
        }
        ep++; gbar(ep * NBLK);

        // ---- P3: attn(t) [0..31] ; ro(t-1) [32..127] ; rored(t-2) [128..159] --
        if (bid < 32) {
            attn_task(t, bid, src_seq, Wq, w_cov, v_att, W_copy, b_copy,
                      bx, bh, out, sm);
        } else if (t >= 1 && bid < 128) {
            int r = (bid - 32)*2 + half;     // 0..191
            gemm_tile(2, t-1, r % 12, (r / 12) * 32, utid, Wx, Wh, W_read, sA);
        } else if (t >= 2 && bid < 160) {
            rored_task(t-2, bid - 128, b_read, out);
        }
        ep++; gbar(ep * NBLK);
    }

    // ---- tail A: ro(T-1) + rored(T-2) ----
    if (bid >= 32 && bid < 128) {
        int r = (bid - 32)*2 + half;
        gemm_tile(2, T-1, r % 12, (r / 12) * 32, utid, Wx, Wh, W_read, sA);
    } else if (bid < 32) {
        rored_task(T-2, bid, b_read, out);
    }
    ep++; gbar(ep * NBLK);
    // ---- tail B: rored(T-1) ----
    if (bid < 32) rored_task(T-1, bid, b_read, out);
}

// ---------------- launch ------------------------------------------------------

extern "C" void kernel_launch(void* const* d_in, const int* in_sizes, int n_in,
                              void* d_out, int out_size)
{
    const int*   tgt      = (const int*)  d_in[0];
    const int*   src      = (const int*)  d_in[1];
    const float* enc      = (const float*)d_in[2];
    const float* hidden   = (const float*)d_in[3];
    const float* word_emb = (const float*)d_in[4];
    const float* W_init   = (const float*)d_in[5];
    const float* b_init   = (const float*)d_in[6];
    const float* Wx       = (const float*)d_in[7];
    const float* Wh       = (const float*)d_in[8];
    const float* bx       = (const float*)d_in[9];
    const float* bh       = (const float*)d_in[10];
    const float* Wc       = (const float*)d_in[11];
    const float* Wq       = (const float*)d_in[12];
    const float* w_cov    = (const float*)d_in[13];
    const float* v_att    = (const float*)d_in[14];
    const float* W_copy   = (const float*)d_in[15];
    const float* b_copy   = (const float*)d_in[16];
    const float* W_read   = (const float*)d_in[17];
    const float* b_read   = (const float*)d_in[18];
    float* out = (float*)d_out;

    k_embed<<<T*B, 128>>>(tgt, word_emb);
    k_pre<<<(B*S)/16, dim3(16,16)>>>(enc, Wc);
    k_encw<<<(B*S)/8, 256>>>(enc, W_copy);
    k_init0<<<64, 256>>>();

    k_persist<<<NBLK, 256, 2*32*132*sizeof(float)>>>(
        src, enc, hidden, W_init, b_init, Wx, Wh, bx, bh,
        Wq, w_cov, v_att, W_copy, b_copy, W_read, b_read, out);
}